// round 2
// baseline (speedup 1.0000x reference)
#include <cuda_runtime.h>

// ---------------- problem constants ----------------
#define NB    384          // proposals per image
#define NC    11           // classes incl background
#define NFG   10           // foreground classes
#define NIMG  2            // images
#define NGRP  (NIMG*NFG)   // 20 NMS groups
#define MTOT  (NIMG*NB)    // 768 proposals
#define DET   100
#define MASKW 12           // ceil(384/32)
#define EPSF  1e-8f
#define SCORE_TH 0.05f
#define NMS_TH   0.5f
#define XFORM_CLIP 4.135166556742356f   // log(1000/16)
#define FULLM 0xFFFFFFFFu

// ---------------- device scratch (no allocs allowed) ----------------
__device__ float g_scores[NGRP*NB];
__device__ float g_boxes [NGRP*NB*5];
__device__ float g_corn  [NGRP*NB*8];
__device__ float g_area  [NGRP*NB];
__device__ float g_rad   [NGRP*NB];
__device__ float g_kept  [NGRP*NB];

// ---------------- kernel 1: softmax + decode + corners ----------------
__global__ void k_decode(const float* __restrict__ logits,
                         const float* __restrict__ reg,
                         const float* __restrict__ rr)
{
    int m = blockIdx.x*blockDim.x + threadIdx.x;
    if (m >= MTOT) return;

    float l[NC];
    float mx = -1e30f;
    #pragma unroll
    for (int c=0;c<NC;c++){ l[c] = logits[m*NC+c]; mx = fmaxf(mx, l[c]); }
    float s = 0.f;
    #pragma unroll
    for (int c=0;c<NC;c++){ l[c] = expf(l[c]-mx); s += l[c]; }

    float xc = rr[m*5+0], yc = rr[m*5+1];
    float w  = rr[m*5+2], h  = rr[m*5+3], a = rr[m*5+4];
    int b = m / NB, n = m % NB;

    #pragma unroll 1
    for (int c=1;c<NC;c++){
        const float* r = &reg[m*(NC*5) + c*5];
        float dx = r[0]/10.0f;
        float dy = r[1]/10.0f;
        float dw = fminf(r[2]/5.0f, XFORM_CLIP);
        float dh = fminf(r[3]/5.0f, XFORM_CLIP);
        float da = r[4]/1.0f;

        float px = dx*w + xc;
        float py = dy*h + yc;
        float pw = expf(dw)*w;
        float ph = expf(dh)*h;
        float pa = da*(float)(180.0/3.14159265358979323846) + a;
        float x2 = pa + 180.0f;
        float rm = fmodf(x2, 360.0f);
        if (rm < 0.0f) rm += 360.0f;
        pa = rm - 180.0f;

        int g = b*NFG + (c-1);
        int o = g*NB + n;
        g_scores[o]    = l[c]/s;
        g_boxes[o*5+0] = px; g_boxes[o*5+1] = py;
        g_boxes[o*5+2] = pw; g_boxes[o*5+3] = ph; g_boxes[o*5+4] = pa;
        g_area[o]      = pw*ph;
        g_rad[o]       = 0.5f*sqrtf(pw*pw + ph*ph);
        g_kept[o]      = -1.0f;      // reset each replay (graph!)

        float t  = pa*(float)(3.14159265358979323846/180.0);
        float cs = cosf(t), sn = sinf(t);
        float hx = pw*0.5f, hy = ph*0.5f;
        float lx[4] = {-hx, hx, hx, -hx};
        float ly[4] = {-hy, -hy, hy, hy};
        #pragma unroll
        for (int k=0;k<4;k++){
            g_corn[o*8+2*k]   = px + lx[k]*cs - ly[k]*sn;
            g_corn[o*8+2*k+1] = py + lx[k]*sn + ly[k]*cs;
        }
    }
}

// ---------------- rotated-rect intersection (mirrors reference) ----------------
__device__ __forceinline__ float crs(float ax,float ay,float bx,float by){
    return ax*by - ay*bx;
}

__device__ float inter_area_dev(const float* CA, const float* CB)
{
    float ax[4],ay[4],bx4[4],by4[4];
    #pragma unroll
    for (int k=0;k<4;k++){ ax[k]=CA[2*k]; ay[k]=CA[2*k+1]; bx4[k]=CB[2*k]; by4[k]=CB[2*k+1]; }
    float d1x[4],d1y[4],d2x[4],d2y[4];
    #pragma unroll
    for (int k=0;k<4;k++){
        d1x[k]=ax[(k+1)&3]-ax[k];  d1y[k]=ay[(k+1)&3]-ay[k];
        d2x[k]=bx4[(k+1)&3]-bx4[k]; d2y[k]=by4[(k+1)&3]-by4[k];
    }

    float px[24], py[24]; bool ok[24];
    #pragma unroll
    for (int i=0;i<4;i++){
        #pragma unroll
        for (int j=0;j<4;j++){
            float den  = crs(d1x[i],d1y[i],d2x[j],d2y[j]);
            float dfx  = bx4[j]-ax[i], dfy = by4[j]-ay[i];
            float dens = (fabsf(den) < EPSF) ? 1.0f : den;
            float t = crs(dfx,dfy,d2x[j],d2y[j]) / dens;
            float u = crs(dfx,dfy,d1x[i],d1y[i]) / dens;
            bool o = (fabsf(den) >= EPSF) && (t>=0.0f) && (t<=1.0f) && (u>=0.0f) && (u<=1.0f);
            px[4*i+j] = ax[i] + t*d1x[i];
            py[4*i+j] = ay[i] + t*d1y[i];
            ok[4*i+j] = o;
        }
    }
    #pragma unroll
    for (int p=0;p<4;p++){
        bool allpos=true, allneg=true;
        #pragma unroll
        for (int e=0;e<4;e++){
            float cr = crs(d2x[e],d2y[e], ax[p]-bx4[e], ay[p]-by4[e]);
            allpos = allpos && (cr >= -1e-6f);
            allneg = allneg && (cr <=  1e-6f);
        }
        ok[16+p] = allpos || allneg;
        px[16+p] = ax[p]; py[16+p] = ay[p];
    }
    #pragma unroll
    for (int p=0;p<4;p++){
        bool allpos=true, allneg=true;
        #pragma unroll
        for (int e=0;e<4;e++){
            float cr = crs(d1x[e],d1y[e], bx4[p]-ax[e], by4[p]-ay[e]);
            allpos = allpos && (cr >= -1e-6f);
            allneg = allneg && (cr <=  1e-6f);
        }
        ok[20+p] = allpos || allneg;
        px[20+p] = bx4[p]; py[20+p] = by4[p];
    }

    int nv = 0; float cx = 0.0f, cy = 0.0f;
    #pragma unroll
    for (int i=0;i<24;i++) if (ok[i]){ nv++; cx += px[i]; cy += py[i]; }
    if (nv < 3) return 0.0f;
    cx /= (float)nv;  cy /= (float)nv;

    // valid points + ONE centroid vertex at angle +0.0 (all parked points
    // in the reference collapse to this single insertion: cross(c,c)=0)
    float sxp[25], syp[25], sap[25];
    int cnt = 0;
    #pragma unroll
    for (int i=0;i<24;i++) if (ok[i]){
        sxp[cnt]=px[i]; syp[cnt]=py[i];
        sap[cnt]=atan2f(py[i]-cy, px[i]-cx);
        cnt++;
    }
    sxp[cnt]=cx; syp[cnt]=cy; sap[cnt]=0.0f; cnt++;

    for (int k=1;k<cnt;k++){             // stable insertion sort by angle
        float a0=sap[k], x0=sxp[k], y0=syp[k];
        int mo=k-1;
        while (mo>=0 && sap[mo] > a0){
            sap[mo+1]=sap[mo]; sxp[mo+1]=sxp[mo]; syp[mo+1]=syp[mo]; mo--;
        }
        sap[mo+1]=a0; sxp[mo+1]=x0; syp[mo+1]=y0;
    }
    float s = 0.0f;
    for (int i=0;i<cnt;i++){
        int j = (i+1<cnt) ? i+1 : 0;
        s += sxp[i]*syp[j] - syp[i]*sxp[j];
    }
    return 0.5f*fabsf(s);
}

// ---------------- kernel 2: fused per-group sort + pairs + greedy ----------------
__global__ void __launch_bounds__(512) k_nms()
{
    __shared__ unsigned long long skeys[512];
    __shared__ int      svlist[NB];
    __shared__ float    scorn[NB*8];
    __shared__ float    scx[NB], scy[NB], sarea[NB], srad[NB];
    __shared__ unsigned smask[NB*MASKW];
    __shared__ int      rlist[NB];

    int g = blockIdx.x;
    int t = threadIdx.x;

    // ---- build sort keys (desc score, asc idx) ----
    bool val = false;
    unsigned long long v;
    if (t < NB){
        float sc = g_scores[g*NB+t];
        val = sc > SCORE_TH;
        float kf = val ? sc : __int_as_float(0xFF800000);
        unsigned ub = __float_as_uint(kf);
        ub = (ub & 0x80000000u) ? ~ub : (ub | 0x80000000u);
        v = (((unsigned long long)(~ub)) << 32) | (unsigned)t;
    } else {
        v = 0xFFFFFFFF00000000ull | (unsigned)t;
    }
    int vv = __syncthreads_count(val);

    // ---- hybrid bitonic sort, 512 elems (ascending == score desc) ----
    #pragma unroll
    for (int k=2;k<=512;k<<=1){
        #pragma unroll
        for (int j=k>>1;j>=32;j>>=1){
            skeys[t]=v; __syncthreads();
            unsigned long long o = skeys[t^j]; __syncthreads();
            bool up = ((t&k)==0), lower = ((t&j)==0);
            v = ((v<o)==(lower==up)) ? v : o;
        }
        int jmax = (k>>1) < 16 ? (k>>1) : 16;
        #pragma unroll
        for (int j=jmax;j>0;j>>=1){
            unsigned long long o = __shfl_xor_sync(FULLM, v, j);
            bool up = ((t&k)==0), lower = ((t&j)==0);
            v = ((v<o)==(lower==up)) ? v : o;
        }
    }
    skeys[t] = v;
    __syncthreads();

    // ---- permute per-box data into sorted order, zero masks ----
    if (t < vv){
        int n = (int)(skeys[t] & 0xFFFFFFFFull);
        svlist[t] = n;
        int o = g*NB + n;
        #pragma unroll
        for (int k=0;k<8;k++) scorn[t*8+k] = g_corn[o*8+k];
        scx[t]   = g_boxes[o*5+0];
        scy[t]   = g_boxes[o*5+1];
        sarea[t] = g_area[o];
        srad[t]  = g_rad[o];
    }
    for (int w = t; w < vv*MASKW; w += 512) smask[w] = 0u;
    __syncthreads();

    // ---- all valid pairs -> suppression bitmask (shared atomics) ----
    int P = vv*(vv-1)/2;
    for (int p = t; p < P; p += 512){
        int j = (int)((1.0f + sqrtf(1.0f + 8.0f*(float)p))*0.5f);
        while (j*(j-1)/2 > p) j--;
        while ((j+1)*j/2 <= p) j++;
        int i = p - j*(j-1)/2;

        float aA = sarea[i], aB = sarea[j];
        float mn = fminf(aA,aB), sm = aA + aB;
        if (3.0f*mn <= sm*(1.0f - 1e-4f)) continue;       // IoU<=0.5 certain
        float dx = scx[i]-scx[j], dy = scy[i]-scy[j];
        float rr = srad[i]+srad[j];
        if (dx*dx + dy*dy >= rr*rr) continue;             // disjoint
        float inter = inter_area_dev(&scorn[i*8], &scorn[j*8]);
        float iou = inter / (aA + aB - inter + EPSF);
        if (iou > NMS_TH)
            atomicOr(&smask[i*MASKW + (j>>5)], 1u << (j&31));
    }
    __syncthreads();

    // ---- greedy over NONZERO rows only (warp 0) ----
    if (t < 32){
        int lane = t;
        int rcnt = 0;
        for (int base=0; base<vv; base+=32){
            int r = base + lane;
            bool any = false;
            if (r < vv){
                unsigned o = 0u;
                #pragma unroll
                for (int w=0;w<MASKW;w++) o |= smask[r*MASKW+w];
                any = (o != 0u);
            }
            unsigned bal = __ballot_sync(FULLM, any);
            if (any) rlist[rcnt + __popc(bal & ((1u<<lane)-1u))] = r;
            rcnt += __popc(bal);
        }
        unsigned supw = 0u;                       // lane<12 owns sup word
        for (int q=0;q<rcnt;q++){
            int r = rlist[q];
            unsigned cw = __shfl_sync(FULLM, supw, r>>5);
            if (!((cw >> (r&31)) & 1u)){
                if (lane < MASKW) supw |= smask[r*MASKW + lane];
            }
        }
        for (int base=0; base<vv; base+=32){
            int tp = base + lane;
            int src = (tp < vv) ? (tp>>5) : 0;
            unsigned wv = __shfl_sync(FULLM, supw, src);
            if (tp < vv && !((wv >> (tp&31)) & 1u)){
                int n = svlist[tp];
                unsigned ub = ~(unsigned)(skeys[tp] >> 32);
                unsigned bits = (ub & 0x80000000u) ? (ub ^ 0x80000000u) : ~ub;
                g_kept[g*NB+n] = __uint_as_float(bits);
            }
        }
    }
}

// ---------------- kernel 3: per-image compaction + top-100 ----------------
__global__ void __launch_bounds__(512) k_topk(float* __restrict__ out, int out_size)
{
    __shared__ unsigned long long sk[4096];
    __shared__ int scnt;

    int b = blockIdx.x;
    int t = threadIdx.x;
    if (t == 0) scnt = 0;
    __syncthreads();

    for (int f = t; f < NFG*NB; f += 512){
        float sc = g_kept[b*NFG*NB + f];
        if (sc > 0.0f){
            unsigned ub = __float_as_uint(sc) | 0x80000000u;   // sc>0
            unsigned long long key = (((unsigned long long)(~ub)) << 32) | (unsigned)f;
            int p = atomicAdd(&scnt, 1);
            sk[p] = key;
        }
    }
    __syncthreads();
    int K = scnt;
    int P = 128;
    while (P < K) P <<= 1;                         // K <= 3840 -> P <= 4096
    for (int f = K + t; f < P; f += 512) sk[f] = 0xFFFFFFFFFFFFFFFFull;
    __syncthreads();

    for (int k=2;k<=P;k<<=1)
        for (int j=k>>1;j>0;j>>=1){
            for (int p=t;p<P;p+=512){
                int ixj = p ^ j;
                if (ixj > p){
                    unsigned long long A = sk[p], Bv = sk[ixj];
                    if ((A > Bv) == ((p & k) == 0)){ sk[p] = Bv; sk[ixj] = A; }
                }
            }
            __syncthreads();
        }

    if (t < DET){
        unsigned long long key = sk[t];
        unsigned f  = (unsigned)(key & 0xFFFFFFFFull);
        unsigned ub = ~((unsigned)(key >> 32));
        unsigned bits = (ub & 0x80000000u) ? (ub ^ 0x80000000u) : ~ub;
        float sc = __uint_as_float(bits);
        bool okd = (sc > 0.0f);

        float vals[6] = {0.f,0.f,0.f,0.f,0.f,0.f};
        float lab = 0.0f;
        if (okd){
            int bi = b*NFG*NB + (int)f;
            #pragma unroll
            for (int kk=0;kk<5;kk++) vals[kk] = g_boxes[bi*5+kk];
            vals[5] = sc;
            lab = (float)((int)f / NB + 1);
        }
        int base = b*DET*6 + t*6;
        #pragma unroll
        for (int kk=0;kk<6;kk++) if (base+kk < out_size) out[base+kk] = vals[kk];
        int li = NIMG*DET*6 + b*DET + t;
        if (li < out_size) out[li] = lab;
    }
}

// ---------------- launcher ----------------
extern "C" void kernel_launch(void* const* d_in, const int* in_sizes, int n_in,
                              void* d_out, int out_size)
{
    const float* logits = (const float*)d_in[0];   // (768, 11)
    const float* reg    = (const float*)d_in[1];   // (768, 55)
    const float* rr     = (const float*)d_in[2];   // (768, 5)

    k_decode<<<(MTOT+255)/256, 256>>>(logits, reg, rr);
    k_nms   <<<NGRP, 512>>>();
    k_topk  <<<NIMG, 512>>>((float*)d_out, out_size);
}

// round 3
// speedup vs baseline: 2.2478x; 2.2478x over previous
#include <cuda_runtime.h>

// ---------------- problem constants ----------------
#define NB    384          // proposals per image
#define NC    11           // classes incl background
#define NFG   10           // foreground classes
#define NIMG  2            // images
#define NGRP  (NIMG*NFG)   // 20 NMS groups
#define MTOT  (NIMG*NB)    // 768 proposals
#define DET   100
#define MASKW 12           // ceil(384/32)
#define EPSF  1e-8f
#define SCORE_TH 0.05f
#define NMS_TH   0.5f
#define XFORM_CLIP 4.135166556742356f   // log(1000/16)
#define FULLM 0xFFFFFFFFu
#define SUBB  37           // pair-kernel blocks per group

// ---------------- device scratch (no allocs allowed) ----------------
__device__ float    g_scores[NGRP*NB];
__device__ float    g_boxes [NGRP*NB*5];
__device__ float    g_corn  [NGRP*NB*8];
__device__ float    g_area  [NGRP*NB];
__device__ float    g_rad   [NGRP*NB];
__device__ float    g_kept  [NGRP*NB];
// score-sorted (permuted) per-group data, written by k_sort
__device__ int      g_vcnt  [NGRP];
__device__ int      g_vlist [NGRP*NB];
__device__ float    g_psc   [NGRP*NB];
__device__ float    g_pcorn [NGRP*NB*8];
__device__ float    g_pcx   [NGRP*NB];
__device__ float    g_pcy   [NGRP*NB];
__device__ float    g_parea [NGRP*NB];
__device__ float    g_prad  [NGRP*NB];
__device__ unsigned g_mask  [NGRP*NB*MASKW];

// ---------------- kernel 1: softmax + decode + corners (thread per (m,c)) ----------------
__global__ void k_decode(const float* __restrict__ logits,
                         const float* __restrict__ reg,
                         const float* __restrict__ rr)
{
    int tid = blockIdx.x*blockDim.x + threadIdx.x;
    if (tid >= MTOT*NFG) return;
    int m  = tid / NFG;
    int cf = tid % NFG;          // 0..9
    int c  = cf + 1;             // fg class 1..10

    float mx = -1e30f;
    float l[NC];
    #pragma unroll
    for (int k=0;k<NC;k++){ l[k] = logits[m*NC+k]; mx = fmaxf(mx, l[k]); }
    float s = 0.f;
    #pragma unroll
    for (int k=0;k<NC;k++) s += expf(l[k]-mx);
    float prob = expf(l[c]-mx)/s;

    float xc = rr[m*5+0], yc = rr[m*5+1];
    float w  = rr[m*5+2], h  = rr[m*5+3], a = rr[m*5+4];

    const float* r = &reg[m*(NC*5) + c*5];
    float dx = r[0]/10.0f;
    float dy = r[1]/10.0f;
    float dw = fminf(r[2]/5.0f, XFORM_CLIP);
    float dh = fminf(r[3]/5.0f, XFORM_CLIP);
    float da = r[4];

    float px = dx*w + xc;
    float py = dy*h + yc;
    float pw = expf(dw)*w;
    float ph = expf(dh)*h;
    float pa = da*(float)(180.0/3.14159265358979323846) + a;
    float x2 = pa + 180.0f;
    float rm = fmodf(x2, 360.0f);
    if (rm < 0.0f) rm += 360.0f;
    pa = rm - 180.0f;

    int b = m / NB, n = m % NB;
    int g = b*NFG + cf;
    int o = g*NB + n;
    g_scores[o]    = prob;
    g_boxes[o*5+0] = px; g_boxes[o*5+1] = py;
    g_boxes[o*5+2] = pw; g_boxes[o*5+3] = ph; g_boxes[o*5+4] = pa;
    g_area[o]      = pw*ph;
    g_rad[o]       = 0.5f*sqrtf(pw*pw + ph*ph);
    g_kept[o]      = -1.0f;                 // reset each graph replay

    float t  = pa*(float)(3.14159265358979323846/180.0);
    float cs = cosf(t), sn = sinf(t);
    float hx = pw*0.5f, hy = ph*0.5f;
    float lx[4] = {-hx, hx, hx, -hx};
    float ly[4] = {-hy, -hy, hy, hy};
    #pragma unroll
    for (int k=0;k<4;k++){
        g_corn[o*8+2*k]   = px + lx[k]*cs - ly[k]*sn;
        g_corn[o*8+2*k+1] = py + lx[k]*sn + ly[k]*cs;
    }
}

// ---------------- kernel 2: per-group sort + permute ----------------
__global__ void __launch_bounds__(512) k_sort()
{
    __shared__ unsigned long long skeys[512];
    int g = blockIdx.x;
    int t = threadIdx.x;

    bool val = false;
    unsigned long long v;
    if (t < NB){
        float sc = g_scores[g*NB+t];
        val = sc > SCORE_TH;
        float kf = val ? sc : __int_as_float(0xFF800000);
        unsigned ub = __float_as_uint(kf);
        ub = (ub & 0x80000000u) ? ~ub : (ub | 0x80000000u);
        v = (((unsigned long long)(~ub)) << 32) | (unsigned)t;
    } else {
        v = 0xFFFFFFFF00000000ull | (unsigned)t;
    }
    // zero this group's suppression mask (graph replays!)
    for (int w = t; w < NB*MASKW; w += 512) g_mask[g*NB*MASKW + w] = 0u;
    int vv = __syncthreads_count(val);
    if (t == 0) g_vcnt[g] = vv;

    // hybrid bitonic: shared for j>=32, shfl for j<32 (ascending == score desc)
    #pragma unroll
    for (int k=2;k<=512;k<<=1){
        #pragma unroll
        for (int j=k>>1;j>=32;j>>=1){
            skeys[t]=v; __syncthreads();
            unsigned long long o = skeys[t^j]; __syncthreads();
            bool up = ((t&k)==0), lower = ((t&j)==0);
            v = ((v<o)==(lower==up)) ? v : o;
        }
        int jmax = (k>>1) < 16 ? (k>>1) : 16;
        #pragma unroll
        for (int j=jmax;j>0;j>>=1){
            unsigned long long o = __shfl_xor_sync(FULLM, v, j);
            bool up = ((t&k)==0), lower = ((t&j)==0);
            v = ((v<o)==(lower==up)) ? v : o;
        }
    }

    // permute per-box data into sorted order
    if (t < vv){
        int n = (int)(v & 0xFFFFFFFFull);
        unsigned ub = ~(unsigned)(v >> 32);
        unsigned bits = (ub & 0x80000000u) ? (ub ^ 0x80000000u) : ~ub;
        int o = g*NB + n;
        int q = g*NB + t;
        g_vlist[q] = n;
        g_psc[q]   = __uint_as_float(bits);
        #pragma unroll
        for (int k=0;k<8;k++) g_pcorn[q*8+k] = g_corn[o*8+k];
        g_pcx[q]   = g_boxes[o*5+0];
        g_pcy[q]   = g_boxes[o*5+1];
        g_parea[q] = g_area[o];
        g_prad[q]  = g_rad[o];
    }
}

// ---------------- rotated-rect intersection (mirrors reference) ----------------
__device__ __forceinline__ float crs(float ax,float ay,float bx,float by){
    return ax*by - ay*bx;
}

__device__ float inter_area_dev(const float* __restrict__ CA, const float* __restrict__ CB)
{
    float ax[4],ay[4],bx4[4],by4[4];
    #pragma unroll
    for (int k=0;k<4;k++){ ax[k]=CA[2*k]; ay[k]=CA[2*k+1]; bx4[k]=CB[2*k]; by4[k]=CB[2*k+1]; }
    float d1x[4],d1y[4],d2x[4],d2y[4];
    #pragma unroll
    for (int k=0;k<4;k++){
        d1x[k]=ax[(k+1)&3]-ax[k];  d1y[k]=ay[(k+1)&3]-ay[k];
        d2x[k]=bx4[(k+1)&3]-bx4[k]; d2y[k]=by4[(k+1)&3]-by4[k];
    }

    float px[24], py[24]; bool ok[24];
    #pragma unroll
    for (int i=0;i<4;i++){
        #pragma unroll
        for (int j=0;j<4;j++){
            float den  = crs(d1x[i],d1y[i],d2x[j],d2y[j]);
            float dfx  = bx4[j]-ax[i], dfy = by4[j]-ay[i];
            float dens = (fabsf(den) < EPSF) ? 1.0f : den;
            float t = crs(dfx,dfy,d2x[j],d2y[j]) / dens;
            float u = crs(dfx,dfy,d1x[i],d1y[i]) / dens;
            bool o = (fabsf(den) >= EPSF) && (t>=0.0f) && (t<=1.0f) && (u>=0.0f) && (u<=1.0f);
            px[4*i+j] = ax[i] + t*d1x[i];
            py[4*i+j] = ay[i] + t*d1y[i];
            ok[4*i+j] = o;
        }
    }
    #pragma unroll
    for (int p=0;p<4;p++){
        bool allpos=true, allneg=true;
        #pragma unroll
        for (int e=0;e<4;e++){
            float cr = crs(d2x[e],d2y[e], ax[p]-bx4[e], ay[p]-by4[e]);
            allpos = allpos && (cr >= -1e-6f);
            allneg = allneg && (cr <=  1e-6f);
        }
        ok[16+p] = allpos || allneg;
        px[16+p] = ax[p]; py[16+p] = ay[p];
    }
    #pragma unroll
    for (int p=0;p<4;p++){
        bool allpos=true, allneg=true;
        #pragma unroll
        for (int e=0;e<4;e++){
            float cr = crs(d1x[e],d1y[e], bx4[p]-ax[e], by4[p]-ay[e]);
            allpos = allpos && (cr >= -1e-6f);
            allneg = allneg && (cr <=  1e-6f);
        }
        ok[20+p] = allpos || allneg;
        px[20+p] = bx4[p]; py[20+p] = by4[p];
    }

    int nv = 0; float cx = 0.0f, cy = 0.0f;
    #pragma unroll
    for (int i=0;i<24;i++) if (ok[i]){ nv++; cx += px[i]; cy += py[i]; }
    if (nv < 3) return 0.0f;
    cx /= (float)nv;  cy /= (float)nv;

    // valid points + ONE centroid vertex at angle +0.0 (all parked points
    // in the reference collapse to this single insertion: cross(c,c)=0)
    float sxp[25], syp[25], sap[25];
    int cnt = 0;
    #pragma unroll
    for (int i=0;i<24;i++) if (ok[i]){
        sxp[cnt]=px[i]; syp[cnt]=py[i];
        sap[cnt]=atan2f(py[i]-cy, px[i]-cx);
        cnt++;
    }
    sxp[cnt]=cx; syp[cnt]=cy; sap[cnt]=0.0f; cnt++;

    for (int k=1;k<cnt;k++){             // stable insertion sort by angle
        float a0=sap[k], x0=sxp[k], y0=syp[k];
        int mo=k-1;
        while (mo>=0 && sap[mo] > a0){
            sap[mo+1]=sap[mo]; sxp[mo+1]=sxp[mo]; syp[mo+1]=syp[mo]; mo--;
        }
        sap[mo+1]=a0; sxp[mo+1]=x0; syp[mo+1]=y0;
    }
    float s = 0.0f;
    for (int i=0;i<cnt;i++){
        int j = (i+1<cnt) ? i+1 : 0;
        s += sxp[i]*syp[j] - syp[i]*sxp[j];
    }
    return 0.5f*fabsf(s);
}

// ---------------- kernel 3: all valid pairs -> suppression bitmask ----------------
__global__ void __launch_bounds__(256) k_pairs()
{
    int g   = blockIdx.x / SUBB;
    int sub = blockIdx.x % SUBB;
    int v = g_vcnt[g];
    int P = v*(v-1)/2;
    int base = g*NB;
    for (int p = sub*blockDim.x + threadIdx.x; p < P; p += SUBB*256){
        int j = (int)((1.0f + sqrtf(1.0f + 8.0f*(float)p))*0.5f);
        while (j*(j-1)/2 > p) j--;
        while ((j+1)*j/2 <= p) j++;
        int i = p - j*(j-1)/2;

        float aA = g_parea[base+i], aB = g_parea[base+j];
        float mn = fminf(aA,aB), sm = aA + aB;
        if (3.0f*mn <= sm*(1.0f - 1e-4f)) continue;      // IoU<=0.5 certain
        float dx = g_pcx[base+i]-g_pcx[base+j];
        float dy = g_pcy[base+i]-g_pcy[base+j];
        float rr = g_prad[base+i]+g_prad[base+j];
        if (dx*dx + dy*dy >= rr*rr) continue;            // disjoint
        float inter = inter_area_dev(&g_pcorn[(base+i)*8], &g_pcorn[(base+j)*8]);
        float iou = inter / (aA + aB - inter + EPSF);
        if (iou > NMS_TH)
            atomicOr(&g_mask[(base+i)*MASKW + (j>>5)], 1u << (j&31));
    }
}

// ---------------- kernel 4: serial greedy, nonzero-row compaction ----------------
__global__ void k_greedy()
{
    __shared__ unsigned sm[NB*MASKW];
    __shared__ int rlist[NB];
    int g    = blockIdx.x;
    int lane = threadIdx.x;              // 32 threads
    int v = g_vcnt[g];
    for (int w = lane; w < v*MASKW; w += 32) sm[w] = g_mask[g*NB*MASKW + w];
    __syncwarp();

    // compact rows that suppress anything
    int rcnt = 0;
    for (int b=0; b<v; b+=32){
        int r = b + lane;
        bool any = false;
        if (r < v){
            unsigned o = 0u;
            #pragma unroll
            for (int w=0;w<MASKW;w++) o |= sm[r*MASKW+w];
            any = (o != 0u);
        }
        unsigned bal = __ballot_sync(FULLM, any);
        if (any) rlist[rcnt + __popc(bal & ((1u<<lane)-1u))] = r;
        rcnt += __popc(bal);
    }

    unsigned supw = 0u;                  // lane<12 owns suppression word lane
    for (int q=0;q<rcnt;q++){
        int r = rlist[q];
        unsigned cw = __shfl_sync(FULLM, supw, r>>5);
        if (!((cw >> (r&31)) & 1u)){
            if (lane < MASKW) supw |= sm[r*MASKW + lane];
        }
    }
    for (int b=0; b<v; b+=32){
        int tp = b + lane;
        int src = (tp < v) ? (tp>>5) : 0;
        unsigned wv = __shfl_sync(FULLM, supw, src);
        if (tp < v && !((wv >> (tp&31)) & 1u)){
            int n = g_vlist[g*NB+tp];
            g_kept[g*NB+n] = g_psc[g*NB+tp];
        }
    }
}

// ---------------- kernel 5: per-image compaction + top-100 ----------------
__global__ void __launch_bounds__(512) k_topk(float* __restrict__ out, int out_size)
{
    __shared__ unsigned long long sk[4096];
    __shared__ int scnt;

    int b = blockIdx.x;
    int t = threadIdx.x;
    if (t == 0) scnt = 0;
    __syncthreads();

    for (int f = t; f < NFG*NB; f += 512){
        float sc = g_kept[b*NFG*NB + f];
        if (sc > 0.0f){
            unsigned ub = __float_as_uint(sc) | 0x80000000u;   // sc>0
            unsigned long long key = (((unsigned long long)(~ub)) << 32) | (unsigned)f;
            int p = atomicAdd(&scnt, 1);
            sk[p] = key;
        }
    }
    __syncthreads();
    int K = scnt;
    int P = 128;
    while (P < K) P <<= 1;                         // K <= 3840 -> P <= 4096
    for (int f = K + t; f < P; f += 512) sk[f] = 0xFFFFFFFFFFFFFFFFull;
    __syncthreads();

    for (int k=2;k<=P;k<<=1)
        for (int j=k>>1;j>0;j>>=1){
            for (int p=t;p<P;p+=512){
                int ixj = p ^ j;
                if (ixj > p){
                    unsigned long long A = sk[p], Bv = sk[ixj];
                    if ((A > Bv) == ((p & k) == 0)){ sk[p] = Bv; sk[ixj] = A; }
                }
            }
            __syncthreads();
        }

    if (t < DET){
        unsigned long long key = (t < P) ? sk[t] : 0xFFFFFFFFFFFFFFFFull;
        unsigned f  = (unsigned)(key & 0xFFFFFFFFull);
        unsigned ub = ~((unsigned)(key >> 32));
        unsigned bits = (ub & 0x80000000u) ? (ub ^ 0x80000000u) : ~ub;
        float sc = __uint_as_float(bits);
        bool okd = (t < K) && (sc > 0.0f);

        float vals[6] = {0.f,0.f,0.f,0.f,0.f,0.f};
        float lab = 0.0f;
        if (okd){
            int bi = b*NFG*NB + (int)f;
            #pragma unroll
            for (int kk=0;kk<5;kk++) vals[kk] = g_boxes[bi*5+kk];
            vals[5] = sc;
            lab = (float)((int)f / NB + 1);
        }
        int base = b*DET*6 + t*6;
        #pragma unroll
        for (int kk=0;kk<6;kk++) if (base+kk < out_size) out[base+kk] = vals[kk];
        int li = NIMG*DET*6 + b*DET + t;
        if (li < out_size) out[li] = lab;
    }
}

// ---------------- launcher ----------------
extern "C" void kernel_launch(void* const* d_in, const int* in_sizes, int n_in,
                              void* d_out, int out_size)
{
    const float* logits = (const float*)d_in[0];   // (768, 11)
    const float* reg    = (const float*)d_in[1];   // (768, 55)
    const float* rr     = (const float*)d_in[2];   // (768, 5)

    k_decode<<<(MTOT*NFG+255)/256, 256>>>(logits, reg, rr);
    k_sort  <<<NGRP, 512>>>();
    k_pairs <<<NGRP*SUBB, 256>>>();
    k_greedy<<<NGRP, 32>>>();
    k_topk  <<<NIMG, 512>>>((float*)d_out, out_size);
}

// round 4
// speedup vs baseline: 2.3731x; 1.0557x over previous
#include <cuda_runtime.h>

// ---------------- problem constants ----------------
#define NB    384          // proposals per image
#define NC    11           // classes incl background
#define NFG   10           // foreground classes
#define NIMG  2            // images
#define NGRP  (NIMG*NFG)   // 20 NMS groups
#define MTOT  (NIMG*NB)    // 768 proposals
#define DET   100
#define MASKW 12           // ceil(384/32)
#define EPSF  1e-8f
#define SCORE_TH 0.05f
#define NMS_TH   0.5f
#define XFORM_CLIP 4.135166556742356f   // log(1000/16)
#define FULLM 0xFFFFFFFFu
#define SUBB  37           // pair-kernel blocks per group

// ---------------- device scratch (no allocs allowed) ----------------
__device__ float    g_scores[NGRP*NB];
__device__ float    g_boxes [NGRP*NB*5];
__device__ float    g_corn  [NGRP*NB*8];
__device__ float    g_area  [NGRP*NB];
__device__ float    g_rad   [NGRP*NB];
__device__ float    g_kept  [NGRP*NB];
// score-sorted (permuted) per-group data, written by k_sort
__device__ int      g_vcnt  [NGRP];
__device__ int      g_vlist [NGRP*NB];
__device__ float    g_psc   [NGRP*NB];
__device__ float4   g_pcorn4[NGRP*NB*2];   // corners as 2x float4
__device__ float4   g_pmeta [NGRP*NB];     // (cx, cy, area, rad)
__device__ unsigned g_mask  [NGRP*NB*MASKW];

// ---------------- kernel 1: softmax + decode + corners (thread per (m,c)) ----------------
__global__ void k_decode(const float* __restrict__ logits,
                         const float* __restrict__ reg,
                         const float* __restrict__ rr)
{
    int tid = blockIdx.x*blockDim.x + threadIdx.x;
    if (tid >= MTOT*NFG) return;
    int m  = tid / NFG;
    int cf = tid % NFG;          // 0..9
    int c  = cf + 1;             // fg class 1..10

    float mx = -1e30f;
    float l[NC];
    #pragma unroll
    for (int k=0;k<NC;k++){ l[k] = __ldg(&logits[m*NC+k]); mx = fmaxf(mx, l[k]); }
    float s = 0.f;
    #pragma unroll
    for (int k=0;k<NC;k++) s += expf(l[k]-mx);
    float prob = expf(l[c]-mx)/s;

    float xc = __ldg(&rr[m*5+0]), yc = __ldg(&rr[m*5+1]);
    float w  = __ldg(&rr[m*5+2]), h  = __ldg(&rr[m*5+3]), a = __ldg(&rr[m*5+4]);

    const float* r = &reg[m*(NC*5) + c*5];
    float dx = __ldg(&r[0])/10.0f;
    float dy = __ldg(&r[1])/10.0f;
    float dw = fminf(__ldg(&r[2])/5.0f, XFORM_CLIP);
    float dh = fminf(__ldg(&r[3])/5.0f, XFORM_CLIP);
    float da = __ldg(&r[4]);

    float px = dx*w + xc;
    float py = dy*h + yc;
    float pw = expf(dw)*w;
    float ph = expf(dh)*h;
    float pa = da*(float)(180.0/3.14159265358979323846) + a;
    float x2 = pa + 180.0f;
    float rm = fmodf(x2, 360.0f);
    if (rm < 0.0f) rm += 360.0f;
    pa = rm - 180.0f;

    int b = m / NB, n = m % NB;
    int g = b*NFG + cf;
    int o = g*NB + n;
    g_scores[o]    = prob;
    g_boxes[o*5+0] = px; g_boxes[o*5+1] = py;
    g_boxes[o*5+2] = pw; g_boxes[o*5+3] = ph; g_boxes[o*5+4] = pa;
    g_area[o]      = pw*ph;
    g_rad[o]       = 0.5f*sqrtf(pw*pw + ph*ph);
    g_kept[o]      = -1.0f;                 // reset each graph replay

    float t  = pa*(float)(3.14159265358979323846/180.0);
    float cs = cosf(t), sn = sinf(t);
    float hx = pw*0.5f, hy = ph*0.5f;
    float lx[4] = {-hx, hx, hx, -hx};
    float ly[4] = {-hy, -hy, hy, hy};
    #pragma unroll
    for (int k=0;k<4;k++){
        g_corn[o*8+2*k]   = px + lx[k]*cs - ly[k]*sn;
        g_corn[o*8+2*k+1] = py + lx[k]*sn + ly[k]*cs;
    }
}

// ---------------- kernel 2: per-group sort + permute ----------------
__global__ void __launch_bounds__(512) k_sort()
{
    __shared__ unsigned long long skeys[512];
    int g = blockIdx.x;
    int t = threadIdx.x;

    bool val = false;
    unsigned long long v;
    if (t < NB){
        float sc = g_scores[g*NB+t];
        val = sc > SCORE_TH;
        float kf = val ? sc : __int_as_float(0xFF800000);
        unsigned ub = __float_as_uint(kf);
        ub = (ub & 0x80000000u) ? ~ub : (ub | 0x80000000u);
        v = (((unsigned long long)(~ub)) << 32) | (unsigned)t;
    } else {
        v = 0xFFFFFFFF00000000ull | (unsigned)t;
    }
    // zero this group's suppression mask (graph replays!)
    for (int w = t; w < NB*MASKW; w += 512) g_mask[g*NB*MASKW + w] = 0u;
    int vv = __syncthreads_count(val);
    if (t == 0) g_vcnt[g] = vv;

    // hybrid bitonic: shared for j>=32, shfl for j<32 (ascending == score desc)
    #pragma unroll
    for (int k=2;k<=512;k<<=1){
        #pragma unroll
        for (int j=k>>1;j>=32;j>>=1){
            skeys[t]=v; __syncthreads();
            unsigned long long o = skeys[t^j]; __syncthreads();
            bool up = ((t&k)==0), lower = ((t&j)==0);
            v = ((v<o)==(lower==up)) ? v : o;
        }
        int jmax = (k>>1) < 16 ? (k>>1) : 16;
        #pragma unroll
        for (int j=jmax;j>0;j>>=1){
            unsigned long long o = __shfl_xor_sync(FULLM, v, j);
            bool up = ((t&k)==0), lower = ((t&j)==0);
            v = ((v<o)==(lower==up)) ? v : o;
        }
    }

    // permute per-box data into sorted order (vectorized writes)
    if (t < vv){
        int n = (int)(v & 0xFFFFFFFFull);
        unsigned ub = ~(unsigned)(v >> 32);
        unsigned bits = (ub & 0x80000000u) ? (ub ^ 0x80000000u) : ~ub;
        int o = g*NB + n;
        int q = g*NB + t;
        g_vlist[q] = n;
        g_psc[q]   = __uint_as_float(bits);
        const float* cp = &g_corn[o*8];
        g_pcorn4[q*2+0] = make_float4(cp[0],cp[1],cp[2],cp[3]);
        g_pcorn4[q*2+1] = make_float4(cp[4],cp[5],cp[6],cp[7]);
        g_pmeta[q] = make_float4(g_boxes[o*5+0], g_boxes[o*5+1], g_area[o], g_rad[o]);
    }
}

// ---------------- rotated-rect intersection (mirrors reference) ----------------
__device__ __forceinline__ float crs(float ax,float ay,float bx,float by){
    return ax*by - ay*bx;
}

__device__ float inter_area_dev(const float* CA, const float* CB)
{
    float ax[4],ay[4],bx4[4],by4[4];
    #pragma unroll
    for (int k=0;k<4;k++){ ax[k]=CA[2*k]; ay[k]=CA[2*k+1]; bx4[k]=CB[2*k]; by4[k]=CB[2*k+1]; }
    float d1x[4],d1y[4],d2x[4],d2y[4];
    #pragma unroll
    for (int k=0;k<4;k++){
        d1x[k]=ax[(k+1)&3]-ax[k];  d1y[k]=ay[(k+1)&3]-ay[k];
        d2x[k]=bx4[(k+1)&3]-bx4[k]; d2y[k]=by4[(k+1)&3]-by4[k];
    }

    float px[24], py[24]; bool ok[24];
    #pragma unroll
    for (int i=0;i<4;i++){
        #pragma unroll
        for (int j=0;j<4;j++){
            float den  = crs(d1x[i],d1y[i],d2x[j],d2y[j]);
            float dfx  = bx4[j]-ax[i], dfy = by4[j]-ay[i];
            float dens = (fabsf(den) < EPSF) ? 1.0f : den;
            float t = crs(dfx,dfy,d2x[j],d2y[j]) / dens;
            float u = crs(dfx,dfy,d1x[i],d1y[i]) / dens;
            bool o = (fabsf(den) >= EPSF) && (t>=0.0f) && (t<=1.0f) && (u>=0.0f) && (u<=1.0f);
            px[4*i+j] = ax[i] + t*d1x[i];
            py[4*i+j] = ay[i] + t*d1y[i];
            ok[4*i+j] = o;
        }
    }
    #pragma unroll
    for (int p=0;p<4;p++){
        bool allpos=true, allneg=true;
        #pragma unroll
        for (int e=0;e<4;e++){
            float cr = crs(d2x[e],d2y[e], ax[p]-bx4[e], ay[p]-by4[e]);
            allpos = allpos && (cr >= -1e-6f);
            allneg = allneg && (cr <=  1e-6f);
        }
        ok[16+p] = allpos || allneg;
        px[16+p] = ax[p]; py[16+p] = ay[p];
    }
    #pragma unroll
    for (int p=0;p<4;p++){
        bool allpos=true, allneg=true;
        #pragma unroll
        for (int e=0;e<4;e++){
            float cr = crs(d1x[e],d1y[e], bx4[p]-ax[e], by4[p]-ay[e]);
            allpos = allpos && (cr >= -1e-6f);
            allneg = allneg && (cr <=  1e-6f);
        }
        ok[20+p] = allpos || allneg;
        px[20+p] = bx4[p]; py[20+p] = by4[p];
    }

    int nv = 0; float cx = 0.0f, cy = 0.0f;
    #pragma unroll
    for (int i=0;i<24;i++) if (ok[i]){ nv++; cx += px[i]; cy += py[i]; }
    if (nv < 3) return 0.0f;
    cx /= (float)nv;  cy /= (float)nv;

    // valid points + ONE centroid vertex at angle +0.0 (all parked points
    // in the reference collapse to this single insertion: cross(c,c)=0)
    float sxp[25], syp[25], sap[25];
    int cnt = 0;
    #pragma unroll
    for (int i=0;i<24;i++) if (ok[i]){
        sxp[cnt]=px[i]; syp[cnt]=py[i];
        sap[cnt]=atan2f(py[i]-cy, px[i]-cx);
        cnt++;
    }
    sxp[cnt]=cx; syp[cnt]=cy; sap[cnt]=0.0f; cnt++;

    for (int k=1;k<cnt;k++){             // stable insertion sort by angle
        float a0=sap[k], x0=sxp[k], y0=syp[k];
        int mo=k-1;
        while (mo>=0 && sap[mo] > a0){
            sap[mo+1]=sap[mo]; sxp[mo+1]=sxp[mo]; syp[mo+1]=syp[mo]; mo--;
        }
        sap[mo+1]=a0; sxp[mo+1]=x0; syp[mo+1]=y0;
    }
    float s = 0.0f;
    for (int i=0;i<cnt;i++){
        int j = (i+1<cnt) ? i+1 : 0;
        s += sxp[i]*syp[j] - syp[i]*sxp[j];
    }
    return 0.5f*fabsf(s);
}

// ---------------- kernel 3: all valid pairs -> suppression bitmask ----------------
__global__ void __launch_bounds__(256) k_pairs()
{
    int g   = blockIdx.x / SUBB;
    int sub = blockIdx.x % SUBB;
    int v = g_vcnt[g];
    int P = v*(v-1)/2;
    int base = g*NB;
    for (int p = sub*blockDim.x + threadIdx.x; p < P; p += SUBB*256){
        int j = (int)((1.0f + sqrtf(1.0f + 8.0f*(float)p))*0.5f);
        while (j*(j-1)/2 > p) j--;
        while ((j+1)*j/2 <= p) j++;
        int i = p - j*(j-1)/2;

        float4 mi = g_pmeta[base+i];
        float4 mj = g_pmeta[base+j];
        float aA = mi.z, aB = mj.z;
        float mn = fminf(aA,aB), sm = aA + aB;
        if (3.0f*mn <= sm*(1.0f - 1e-4f)) continue;      // IoU<=0.5 certain
        float dx = mi.x-mj.x, dy = mi.y-mj.y;
        float rr = mi.w+mj.w;
        if (dx*dx + dy*dy >= rr*rr) continue;            // disjoint
        float4 ca0 = g_pcorn4[(base+i)*2+0], ca1 = g_pcorn4[(base+i)*2+1];
        float4 cb0 = g_pcorn4[(base+j)*2+0], cb1 = g_pcorn4[(base+j)*2+1];
        float CA[8] = {ca0.x,ca0.y,ca0.z,ca0.w,ca1.x,ca1.y,ca1.z,ca1.w};
        float CB[8] = {cb0.x,cb0.y,cb0.z,cb0.w,cb1.x,cb1.y,cb1.z,cb1.w};
        float inter = inter_area_dev(CA, CB);
        float iou = inter / (aA + aB - inter + EPSF);
        if (iou > NMS_TH)
            atomicOr(&g_mask[(base+i)*MASKW + (j>>5)], 1u << (j&31));
    }
}

// ---------------- kernel 4: greedy — parallel mask load, warp-0 serial chain ----------------
__global__ void __launch_bounds__(256) k_greedy()
{
    __shared__ unsigned sm[NB*MASKW];
    __shared__ unsigned char sany[NB];
    __shared__ int rlist[NB];
    int g = blockIdx.x;
    int t = threadIdx.x;
    int v = g_vcnt[g];

    for (int w = t; w < v*MASKW; w += 256) sm[w] = g_mask[g*NB*MASKW + w];
    __syncthreads();
    for (int r = t; r < v; r += 256){
        unsigned o = 0u;
        #pragma unroll
        for (int w=0;w<MASKW;w++) o |= sm[r*MASKW+w];
        sany[r] = (o != 0u);
    }
    __syncthreads();

    if (t < 32){
        int lane = t;
        int rcnt = 0;
        for (int b=0; b<v; b+=32){
            int r = b + lane;
            bool any = (r < v) && sany[r];
            unsigned bal = __ballot_sync(FULLM, any);
            if (any) rlist[rcnt + __popc(bal & ((1u<<lane)-1u))] = r;
            rcnt += __popc(bal);
        }
        unsigned supw = 0u;                  // lane<12 owns suppression word lane
        for (int q=0;q<rcnt;q++){
            int r = rlist[q];
            unsigned cw = __shfl_sync(FULLM, supw, r>>5);
            if (!((cw >> (r&31)) & 1u)){
                if (lane < MASKW) supw |= sm[r*MASKW + lane];
            }
        }
        for (int b=0; b<v; b+=32){
            int tp = b + lane;
            int src = (tp < v) ? (tp>>5) : 0;
            unsigned wv = __shfl_sync(FULLM, supw, src);
            if (tp < v && !((wv >> (tp&31)) & 1u)){
                int n = g_vlist[g*NB+tp];
                g_kept[g*NB+n] = g_psc[g*NB+tp];
            }
        }
    }
}

// ---------------- kernel 5: per-image compaction + top-100 ----------------
__global__ void __launch_bounds__(512) k_topk(float* __restrict__ out, int out_size)
{
    __shared__ unsigned long long sk[4096];
    __shared__ int scnt;

    int b = blockIdx.x;
    int t = threadIdx.x;
    if (t == 0) scnt = 0;
    __syncthreads();

    for (int f = t; f < NFG*NB; f += 512){
        float sc = g_kept[b*NFG*NB + f];
        if (sc > 0.0f){
            unsigned ub = __float_as_uint(sc) | 0x80000000u;   // sc>0
            unsigned long long key = (((unsigned long long)(~ub)) << 32) | (unsigned)f;
            int p = atomicAdd(&scnt, 1);
            sk[p] = key;
        }
    }
    __syncthreads();
    int K = scnt;
    int P = 128;
    while (P < K) P <<= 1;                         // K <= 3840 -> P <= 4096
    for (int f = K + t; f < P; f += 512) sk[f] = 0xFFFFFFFFFFFFFFFFull;
    __syncthreads();

    for (int k=2;k<=P;k<<=1)
        for (int j=k>>1;j>0;j>>=1){
            for (int p=t;p<P;p+=512){
                int ixj = p ^ j;
                if (ixj > p){
                    unsigned long long A = sk[p], Bv = sk[ixj];
                    if ((A > Bv) == ((p & k) == 0)){ sk[p] = Bv; sk[ixj] = A; }
                }
            }
            __syncthreads();
        }

    if (t < DET){
        unsigned long long key = (t < P) ? sk[t] : 0xFFFFFFFFFFFFFFFFull;
        unsigned f  = (unsigned)(key & 0xFFFFFFFFull);
        unsigned ub = ~((unsigned)(key >> 32));
        unsigned bits = (ub & 0x80000000u) ? (ub ^ 0x80000000u) : ~ub;
        float sc = __uint_as_float(bits);
        bool okd = (t < K) && (sc > 0.0f);

        float vals[6] = {0.f,0.f,0.f,0.f,0.f,0.f};
        float lab = 0.0f;
        if (okd){
            int bi = b*NFG*NB + (int)f;
            #pragma unroll
            for (int kk=0;kk<5;kk++) vals[kk] = g_boxes[bi*5+kk];
            vals[5] = sc;
            lab = (float)((int)f / NB + 1);
        }
        int base = b*DET*6 + t*6;
        #pragma unroll
        for (int kk=0;kk<6;kk++) if (base+kk < out_size) out[base+kk] = vals[kk];
        int li = NIMG*DET*6 + b*DET + t;
        if (li < out_size) out[li] = lab;
    }
}

// ---------------- launcher ----------------
extern "C" void kernel_launch(void* const* d_in, const int* in_sizes, int n_in,
                              void* d_out, int out_size)
{
    const float* logits = (const float*)d_in[0];   // (768, 11)
    const float* reg    = (const float*)d_in[1];   // (768, 55)
    const float* rr     = (const float*)d_in[2];   // (768, 5)

    k_decode<<<(MTOT*NFG+255)/256, 256>>>(logits, reg, rr);
    k_sort  <<<NGRP, 512>>>();
    k_pairs <<<NGRP*SUBB, 256>>>();
    k_greedy<<<NGRP, 256>>>();
    k_topk  <<<NIMG, 512>>>((float*)d_out, out_size);
}

// round 5
// speedup vs baseline: 2.4663x; 1.0393x over previous
#include <cuda_runtime.h>

// ---------------- problem constants ----------------
#define NB    384          // proposals per image
#define NC    11           // classes incl background
#define NFG   10           // foreground classes
#define NIMG  2            // images
#define NGRP  (NIMG*NFG)   // 20 NMS groups
#define MTOT  (NIMG*NB)    // 768 proposals
#define DET   100
#define MASKW 12           // ceil(384/32)
#define EPSF  1e-8f
#define SCORE_TH 0.05f
#define NMS_TH   0.5f
#define XFORM_CLIP 4.135166556742356f   // log(1000/16)
#define FULLM 0xFFFFFFFFu
#define SUBB  37           // pair-kernel blocks per group

// ---------------- device scratch (no allocs allowed) ----------------
__device__ float    g_boxes [NGRP*NB*5];
__device__ float    g_kept  [NGRP*NB];
__device__ int      g_vcnt  [NGRP];
__device__ int      g_vlist [NGRP*NB];
__device__ float    g_psc   [NGRP*NB];
__device__ float4   g_pcorn4[NGRP*NB*2];   // corners as 2x float4 (sorted order)
__device__ float4   g_pmeta [NGRP*NB];     // (cx, cy, area, rad)  (sorted order)
__device__ unsigned g_mask  [NGRP*NB*MASKW];

// ---------------- kernel 1: fused decode + softmax + sort + permute ----------------
__global__ void __launch_bounds__(512) k_decsort(const float* __restrict__ logits,
                                                 const float* __restrict__ reg,
                                                 const float* __restrict__ rr)
{
    __shared__ unsigned long long skeys[512];
    __shared__ float scorn[NB*8];
    __shared__ float4 smeta[NB];

    int g = blockIdx.x;
    int t = threadIdx.x;
    int b = g / NFG, cf = g % NFG, c = cf + 1;

    bool val = false;
    unsigned long long key;
    if (t < NB){
        int m = b*NB + t;
        float mx = -1e30f;
        float l[NC];
        #pragma unroll
        for (int k=0;k<NC;k++){ l[k] = __ldg(&logits[m*NC+k]); mx = fmaxf(mx, l[k]); }
        float s = 0.f;
        #pragma unroll
        for (int k=0;k<NC;k++) s += expf(l[k]-mx);
        float prob = expf(l[c]-mx)/s;

        float xc = __ldg(&rr[m*5+0]), yc = __ldg(&rr[m*5+1]);
        float w  = __ldg(&rr[m*5+2]), h  = __ldg(&rr[m*5+3]), a = __ldg(&rr[m*5+4]);

        const float* r = &reg[m*(NC*5) + c*5];
        float dx = __ldg(&r[0])/10.0f;
        float dy = __ldg(&r[1])/10.0f;
        float dw = fminf(__ldg(&r[2])/5.0f, XFORM_CLIP);
        float dh = fminf(__ldg(&r[3])/5.0f, XFORM_CLIP);
        float da = __ldg(&r[4]);

        float px = dx*w + xc;
        float py = dy*h + yc;
        float pw = expf(dw)*w;
        float ph = expf(dh)*h;
        float pa = da*(float)(180.0/3.14159265358979323846) + a;
        float x2 = pa + 180.0f;
        float rm = fmodf(x2, 360.0f);
        if (rm < 0.0f) rm += 360.0f;
        pa = rm - 180.0f;

        int o = g*NB + t;
        g_boxes[o*5+0] = px; g_boxes[o*5+1] = py;
        g_boxes[o*5+2] = pw; g_boxes[o*5+3] = ph; g_boxes[o*5+4] = pa;
        g_kept[o]      = -1.0f;                 // reset each graph replay

        smeta[t] = make_float4(px, py, pw*ph, 0.5f*sqrtf(pw*pw + ph*ph));

        float th = pa*(float)(3.14159265358979323846/180.0);
        float cs = cosf(th), sn = sinf(th);
        float hx = pw*0.5f, hy = ph*0.5f;
        float lx[4] = {-hx, hx, hx, -hx};
        float ly[4] = {-hy, -hy, hy, hy};
        #pragma unroll
        for (int k=0;k<4;k++){
            scorn[t*8+2*k]   = px + lx[k]*cs - ly[k]*sn;
            scorn[t*8+2*k+1] = py + lx[k]*sn + ly[k]*cs;
        }

        val = prob > SCORE_TH;
        float kf = val ? prob : __int_as_float(0xFF800000);
        unsigned ub = __float_as_uint(kf);
        ub = (ub & 0x80000000u) ? ~ub : (ub | 0x80000000u);
        key = (((unsigned long long)(~ub)) << 32) | (unsigned)t;
    } else {
        key = 0xFFFFFFFF00000000ull | (unsigned)t;
    }
    // zero this group's suppression mask (graph replays!)
    for (int w = t; w < NB*MASKW; w += 512) g_mask[g*NB*MASKW + w] = 0u;
    int vv = __syncthreads_count(val);
    if (t == 0) g_vcnt[g] = vv;

    // hybrid bitonic: shared for j>=32, shfl for j<32 (ascending == score desc)
    #pragma unroll
    for (int k=2;k<=512;k<<=1){
        #pragma unroll
        for (int j=k>>1;j>=32;j>>=1){
            skeys[t]=key; __syncthreads();
            unsigned long long o = skeys[t^j]; __syncthreads();
            bool up = ((t&k)==0), lower = ((t&j)==0);
            key = ((key<o)==(lower==up)) ? key : o;
        }
        int jmax = (k>>1) < 16 ? (k>>1) : 16;
        #pragma unroll
        for (int j=jmax;j>0;j>>=1){
            unsigned long long o = __shfl_xor_sync(FULLM, key, j);
            bool up = ((t&k)==0), lower = ((t&j)==0);
            key = ((key<o)==(lower==up)) ? key : o;
        }
    }

    // permute per-box data into sorted order (from shared)
    if (t < vv){
        int n = (int)(key & 0xFFFFFFFFull);
        unsigned ub = ~(unsigned)(key >> 32);
        unsigned bits = (ub & 0x80000000u) ? (ub ^ 0x80000000u) : ~ub;
        int q = g*NB + t;
        g_vlist[q] = n;
        g_psc[q]   = __uint_as_float(bits);
        const float* cp = &scorn[n*8];
        g_pcorn4[q*2+0] = make_float4(cp[0],cp[1],cp[2],cp[3]);
        g_pcorn4[q*2+1] = make_float4(cp[4],cp[5],cp[6],cp[7]);
        g_pmeta[q] = smeta[n];
    }
}

// ---------------- rotated-rect intersection (mirrors reference) ----------------
__device__ __forceinline__ float crs(float ax,float ay,float bx,float by){
    return ax*by - ay*bx;
}

__device__ float inter_area_dev(const float* CA, const float* CB)
{
    float ax[4],ay[4],bx4[4],by4[4];
    #pragma unroll
    for (int k=0;k<4;k++){ ax[k]=CA[2*k]; ay[k]=CA[2*k+1]; bx4[k]=CB[2*k]; by4[k]=CB[2*k+1]; }
    float d1x[4],d1y[4],d2x[4],d2y[4];
    #pragma unroll
    for (int k=0;k<4;k++){
        d1x[k]=ax[(k+1)&3]-ax[k];  d1y[k]=ay[(k+1)&3]-ay[k];
        d2x[k]=bx4[(k+1)&3]-bx4[k]; d2y[k]=by4[(k+1)&3]-by4[k];
    }

    float px[24], py[24]; bool ok[24];
    #pragma unroll
    for (int i=0;i<4;i++){
        #pragma unroll
        for (int j=0;j<4;j++){
            float den  = crs(d1x[i],d1y[i],d2x[j],d2y[j]);
            float dfx  = bx4[j]-ax[i], dfy = by4[j]-ay[i];
            float dens = (fabsf(den) < EPSF) ? 1.0f : den;
            float t = crs(dfx,dfy,d2x[j],d2y[j]) / dens;
            float u = crs(dfx,dfy,d1x[i],d1y[i]) / dens;
            bool o = (fabsf(den) >= EPSF) && (t>=0.0f) && (t<=1.0f) && (u>=0.0f) && (u<=1.0f);
            px[4*i+j] = ax[i] + t*d1x[i];
            py[4*i+j] = ay[i] + t*d1y[i];
            ok[4*i+j] = o;
        }
    }
    #pragma unroll
    for (int p=0;p<4;p++){
        bool allpos=true, allneg=true;
        #pragma unroll
        for (int e=0;e<4;e++){
            float cr = crs(d2x[e],d2y[e], ax[p]-bx4[e], ay[p]-by4[e]);
            allpos = allpos && (cr >= -1e-6f);
            allneg = allneg && (cr <=  1e-6f);
        }
        ok[16+p] = allpos || allneg;
        px[16+p] = ax[p]; py[16+p] = ay[p];
    }
    #pragma unroll
    for (int p=0;p<4;p++){
        bool allpos=true, allneg=true;
        #pragma unroll
        for (int e=0;e<4;e++){
            float cr = crs(d1x[e],d1y[e], bx4[p]-ax[e], by4[p]-ay[e]);
            allpos = allpos && (cr >= -1e-6f);
            allneg = allneg && (cr <=  1e-6f);
        }
        ok[20+p] = allpos || allneg;
        px[20+p] = bx4[p]; py[20+p] = by4[p];
    }

    int nv = 0; float cx = 0.0f, cy = 0.0f;
    #pragma unroll
    for (int i=0;i<24;i++) if (ok[i]){ nv++; cx += px[i]; cy += py[i]; }
    if (nv < 3) return 0.0f;
    cx /= (float)nv;  cy /= (float)nv;

    // valid points + ONE centroid vertex at angle +0.0 (all parked points
    // in the reference collapse to this single insertion: cross(c,c)=0)
    float sxp[25], syp[25], sap[25];
    int cnt = 0;
    #pragma unroll
    for (int i=0;i<24;i++) if (ok[i]){
        sxp[cnt]=px[i]; syp[cnt]=py[i];
        sap[cnt]=atan2f(py[i]-cy, px[i]-cx);
        cnt++;
    }
    sxp[cnt]=cx; syp[cnt]=cy; sap[cnt]=0.0f; cnt++;

    for (int k=1;k<cnt;k++){             // stable insertion sort by angle
        float a0=sap[k], x0=sxp[k], y0=syp[k];
        int mo=k-1;
        while (mo>=0 && sap[mo] > a0){
            sap[mo+1]=sap[mo]; sxp[mo+1]=sxp[mo]; syp[mo+1]=syp[mo]; mo--;
        }
        sap[mo+1]=a0; sxp[mo+1]=x0; syp[mo+1]=y0;
    }
    float s = 0.0f;
    for (int i=0;i<cnt;i++){
        int j = (i+1<cnt) ? i+1 : 0;
        s += sxp[i]*syp[j] - syp[i]*sxp[j];
    }
    return 0.5f*fabsf(s);
}

// ---------------- kernel 2: all valid pairs -> suppression bitmask ----------------
__global__ void __launch_bounds__(256) k_pairs()
{
    int g   = blockIdx.x / SUBB;
    int sub = blockIdx.x % SUBB;
    int v = g_vcnt[g];
    int P = v*(v-1)/2;
    int base = g*NB;
    for (int p = sub*blockDim.x + threadIdx.x; p < P; p += SUBB*256){
        int j = (int)((1.0f + sqrtf(1.0f + 8.0f*(float)p))*0.5f);
        while (j*(j-1)/2 > p) j--;
        while ((j+1)*j/2 <= p) j++;
        int i = p - j*(j-1)/2;

        float4 mi = g_pmeta[base+i];
        float4 mj = g_pmeta[base+j];
        float aA = mi.z, aB = mj.z;
        float mn = fminf(aA,aB), sm = aA + aB;
        if (3.0f*mn <= sm*(1.0f - 1e-4f)) continue;      // IoU<=0.5 certain
        float dx = mi.x-mj.x, dy = mi.y-mj.y;
        float rr = mi.w+mj.w;
        if (dx*dx + dy*dy >= rr*rr) continue;            // disjoint
        float4 ca0 = g_pcorn4[(base+i)*2+0], ca1 = g_pcorn4[(base+i)*2+1];
        float4 cb0 = g_pcorn4[(base+j)*2+0], cb1 = g_pcorn4[(base+j)*2+1];
        float CA[8] = {ca0.x,ca0.y,ca0.z,ca0.w,ca1.x,ca1.y,ca1.z,ca1.w};
        float CB[8] = {cb0.x,cb0.y,cb0.z,cb0.w,cb1.x,cb1.y,cb1.z,cb1.w};
        float inter = inter_area_dev(CA, CB);
        float iou = inter / (aA + aB - inter + EPSF);
        if (iou > NMS_TH)
            atomicOr(&g_mask[(base+i)*MASKW + (j>>5)], 1u << (j&31));
    }
}

// ---------------- kernel 3: greedy — block-wise register-serial chain ----------------
__global__ void __launch_bounds__(256) k_greedy()
{
    __shared__ unsigned sm[NB*MASKW];
    __shared__ unsigned sblk[MASKW];
    int g = blockIdx.x;
    int t = threadIdx.x;
    int v = g_vcnt[g];

    for (int w = t; w < v*MASKW; w += 256) sm[w] = g_mask[g*NB*MASKW + w];
    if (t < MASKW) sblk[t] = 0u;
    __syncthreads();

    // per-32-row-block bitmask of suppressor rows (nonzero mask rows)
    int B = (v + 31) & ~31;
    for (int r0 = t; r0 < B; r0 += 256){
        bool any = false;
        if (r0 < v){
            unsigned o = 0u;
            #pragma unroll
            for (int w=0;w<MASKW;w++) o |= sm[r0*MASKW+w];
            any = (o != 0u);
        }
        unsigned bal = __ballot_sync(FULLM, any);
        if ((t & 31) == 0) sblk[r0 >> 5] = bal;
    }
    __syncthreads();

    if (t < 32){
        int lane = t;
        unsigned sup = 0u;                       // lane b owns sup word b
        int nblk = (v + 31) >> 5;
        for (int b=0; b<nblk; b++){
            unsigned sb = sblk[b];
            if (sb == 0u) continue;              // no suppressors in block
            unsigned s = __shfl_sync(FULLM, sup, b);
            if (lane == 0){
                unsigned it = sb;                // ascending row order
                while (it){
                    int l = __ffs(it) - 1; it &= it - 1u;
                    if (!((s >> l) & 1u)) s |= sm[(b*32+l)*MASKW + b];
                }
            }
            s = __shfl_sync(FULLM, s, 0);
            unsigned kept = (~s) & sb;           // kept suppressor rows
            if (lane < MASKW){
                unsigned acc = 0u, it = kept;
                while (it){
                    int l = __ffs(it) - 1; it &= it - 1u;
                    acc |= sm[(b*32+l)*MASKW + lane];
                }
                sup |= acc;
            }
        }
        // write kept scores
        for (int base=0; base<v; base+=32){
            int tp = base + lane;
            int src = (tp < v) ? (tp>>5) : 0;
            unsigned wv = __shfl_sync(FULLM, sup, src);
            if (tp < v && !((wv >> (tp&31)) & 1u)){
                int n = g_vlist[g*NB+tp];
                g_kept[g*NB+n] = g_psc[g*NB+tp];
            }
        }
    }
}

// ---------------- kernel 4: per-image compaction + top-100 ----------------
__global__ void __launch_bounds__(512) k_topk(float* __restrict__ out, int out_size)
{
    __shared__ unsigned long long sk[4096];
    __shared__ int scnt;

    int b = blockIdx.x;
    int t = threadIdx.x;
    if (t == 0) scnt = 0;
    __syncthreads();

    for (int f = t; f < NFG*NB; f += 512){
        float sc = g_kept[b*NFG*NB + f];
        if (sc > 0.0f){
            unsigned ub = __float_as_uint(sc) | 0x80000000u;   // sc>0
            unsigned long long key = (((unsigned long long)(~ub)) << 32) | (unsigned)f;
            int p = atomicAdd(&scnt, 1);
            sk[p] = key;
        }
    }
    __syncthreads();
    int K = scnt;
    int P = 128;
    while (P < K) P <<= 1;                         // K <= 3840 -> P <= 4096
    for (int f = K + t; f < P; f += 512) sk[f] = 0xFFFFFFFFFFFFFFFFull;
    __syncthreads();

    for (int k=2;k<=P;k<<=1)
        for (int j=k>>1;j>0;j>>=1){
            for (int p=t;p<P;p+=512){
                int ixj = p ^ j;
                if (ixj > p){
                    unsigned long long A = sk[p], Bv = sk[ixj];
                    if ((A > Bv) == ((p & k) == 0)){ sk[p] = Bv; sk[ixj] = A; }
                }
            }
            __syncthreads();
        }

    if (t < DET){
        unsigned long long key = (t < P) ? sk[t] : 0xFFFFFFFFFFFFFFFFull;
        unsigned f  = (unsigned)(key & 0xFFFFFFFFull);
        unsigned ub = ~((unsigned)(key >> 32));
        unsigned bits = (ub & 0x80000000u) ? (ub ^ 0x80000000u) : ~ub;
        float sc = __uint_as_float(bits);
        bool okd = (t < K) && (sc > 0.0f);

        float vals[6] = {0.f,0.f,0.f,0.f,0.f,0.f};
        float lab = 0.0f;
        if (okd){
            int bi = b*NFG*NB + (int)f;
            #pragma unroll
            for (int kk=0;kk<5;kk++) vals[kk] = g_boxes[bi*5+kk];
            vals[5] = sc;
            lab = (float)((int)f / NB + 1);
        }
        int base = b*DET*6 + t*6;
        #pragma unroll
        for (int kk=0;kk<6;kk++) if (base+kk < out_size) out[base+kk] = vals[kk];
        int li = NIMG*DET*6 + b*DET + t;
        if (li < out_size) out[li] = lab;
    }
}

// ---------------- launcher ----------------
extern "C" void kernel_launch(void* const* d_in, const int* in_sizes, int n_in,
                              void* d_out, int out_size)
{
    const float* logits = (const float*)d_in[0];   // (768, 11)
    const float* reg    = (const float*)d_in[1];   // (768, 55)
    const float* rr     = (const float*)d_in[2];   // (768, 5)

    k_decsort<<<NGRP, 512>>>(logits, reg, rr);
    k_pairs  <<<NGRP*SUBB, 256>>>();
    k_greedy <<<NGRP, 256>>>();
    k_topk   <<<NIMG, 512>>>((float*)d_out, out_size);
}

// round 6
// speedup vs baseline: 3.4228x; 1.3878x over previous
#include <cuda_runtime.h>

// ---------------- problem constants ----------------
#define NB    384          // proposals per image
#define NC    11           // classes incl background
#define NFG   10           // foreground classes
#define NIMG  2            // images
#define NGRP  (NIMG*NFG)   // 20 NMS groups
#define MTOT  (NIMG*NB)    // 768 proposals
#define DET   100
#define MASKW 12           // ceil(384/32)
#define EPSF  1e-8f
#define SCORE_TH 0.05f
#define NMS_TH   0.5f
#define XFORM_CLIP 4.135166556742356f   // log(1000/16)
#define FULLM 0xFFFFFFFFu
#define SUBB  37           // pair-kernel blocks per group
#define CANDC 2048         // candidate buffer (top-k select)

// ---------------- device scratch (no allocs allowed) ----------------
__device__ float    g_boxes [NGRP*NB*5];
__device__ float    g_kept  [NGRP*NB];
__device__ int      g_vcnt  [NGRP];
__device__ int      g_vlist [NGRP*NB];
__device__ float    g_psc   [NGRP*NB];
__device__ float4   g_pcorn4[NGRP*NB*2];   // corners as 2x float4 (sorted order)
__device__ float4   g_pmeta [NGRP*NB];     // (cx, cy, area, rad)  (sorted order)
__device__ unsigned g_mask  [NGRP*NB*MASKW];

// ---------------- kernel 1: fused decode + softmax + sort + permute ----------------
__global__ void __launch_bounds__(512) k_decsort(const float* __restrict__ logits,
                                                 const float* __restrict__ reg,
                                                 const float* __restrict__ rr)
{
    __shared__ unsigned long long skeys[512];
    __shared__ float scorn[NB*8];
    __shared__ float4 smeta[NB];

    int g = blockIdx.x;
    int t = threadIdx.x;
    int b = g / NFG, cf = g % NFG, c = cf + 1;

    bool val = false;
    unsigned long long key;
    if (t < NB){
        int m = b*NB + t;
        float mx = -1e30f;
        float l[NC];
        #pragma unroll
        for (int k=0;k<NC;k++){ l[k] = __ldg(&logits[m*NC+k]); mx = fmaxf(mx, l[k]); }
        float s = 0.f;
        #pragma unroll
        for (int k=0;k<NC;k++) s += expf(l[k]-mx);
        float prob = expf(l[c]-mx)/s;

        float xc = __ldg(&rr[m*5+0]), yc = __ldg(&rr[m*5+1]);
        float w  = __ldg(&rr[m*5+2]), h  = __ldg(&rr[m*5+3]), a = __ldg(&rr[m*5+4]);

        const float* r = &reg[m*(NC*5) + c*5];
        float dx = __ldg(&r[0])/10.0f;
        float dy = __ldg(&r[1])/10.0f;
        float dw = fminf(__ldg(&r[2])/5.0f, XFORM_CLIP);
        float dh = fminf(__ldg(&r[3])/5.0f, XFORM_CLIP);
        float da = __ldg(&r[4]);

        float px = dx*w + xc;
        float py = dy*h + yc;
        float pw = expf(dw)*w;
        float ph = expf(dh)*h;
        float pa = da*(float)(180.0/3.14159265358979323846) + a;
        float x2 = pa + 180.0f;
        float rm = fmodf(x2, 360.0f);
        if (rm < 0.0f) rm += 360.0f;
        pa = rm - 180.0f;

        int o = g*NB + t;
        g_boxes[o*5+0] = px; g_boxes[o*5+1] = py;
        g_boxes[o*5+2] = pw; g_boxes[o*5+3] = ph; g_boxes[o*5+4] = pa;
        g_kept[o]      = -1.0f;                 // reset each graph replay

        smeta[t] = make_float4(px, py, pw*ph, 0.5f*sqrtf(pw*pw + ph*ph));

        float th = pa*(float)(3.14159265358979323846/180.0);
        float cs = cosf(th), sn = sinf(th);
        float hx = pw*0.5f, hy = ph*0.5f;
        float lx[4] = {-hx, hx, hx, -hx};
        float ly[4] = {-hy, -hy, hy, hy};
        #pragma unroll
        for (int k=0;k<4;k++){
            scorn[t*8+2*k]   = px + lx[k]*cs - ly[k]*sn;
            scorn[t*8+2*k+1] = py + lx[k]*sn + ly[k]*cs;
        }

        val = prob > SCORE_TH;
        float kf = val ? prob : __int_as_float(0xFF800000);
        unsigned ub = __float_as_uint(kf);
        ub = (ub & 0x80000000u) ? ~ub : (ub | 0x80000000u);
        key = (((unsigned long long)(~ub)) << 32) | (unsigned)t;
    } else {
        key = 0xFFFFFFFF00000000ull | (unsigned)t;
    }
    // zero this group's suppression mask (graph replays!)
    for (int w = t; w < NB*MASKW; w += 512) g_mask[g*NB*MASKW + w] = 0u;
    int vv = __syncthreads_count(val);
    if (t == 0) g_vcnt[g] = vv;

    // hybrid bitonic: shared for j>=32, shfl for j<32 (ascending == score desc)
    #pragma unroll
    for (int k=2;k<=512;k<<=1){
        #pragma unroll
        for (int j=k>>1;j>=32;j>>=1){
            skeys[t]=key; __syncthreads();
            unsigned long long o = skeys[t^j]; __syncthreads();
            bool up = ((t&k)==0), lower = ((t&j)==0);
            key = ((key<o)==(lower==up)) ? key : o;
        }
        int jmax = (k>>1) < 16 ? (k>>1) : 16;
        #pragma unroll
        for (int j=jmax;j>0;j>>=1){
            unsigned long long o = __shfl_xor_sync(FULLM, key, j);
            bool up = ((t&k)==0), lower = ((t&j)==0);
            key = ((key<o)==(lower==up)) ? key : o;
        }
    }

    // permute per-box data into sorted order (from shared)
    if (t < vv){
        int n = (int)(key & 0xFFFFFFFFull);
        unsigned ub = ~(unsigned)(key >> 32);
        unsigned bits = (ub & 0x80000000u) ? (ub ^ 0x80000000u) : ~ub;
        int q = g*NB + t;
        g_vlist[q] = n;
        g_psc[q]   = __uint_as_float(bits);
        const float* cp = &scorn[n*8];
        g_pcorn4[q*2+0] = make_float4(cp[0],cp[1],cp[2],cp[3]);
        g_pcorn4[q*2+1] = make_float4(cp[4],cp[5],cp[6],cp[7]);
        g_pmeta[q] = smeta[n];
    }
}

// ---------------- rotated-rect intersection (mirrors reference) ----------------
__device__ __forceinline__ float crs(float ax,float ay,float bx,float by){
    return ax*by - ay*bx;
}

__device__ float inter_area_dev(const float* CA, const float* CB)
{
    float ax[4],ay[4],bx4[4],by4[4];
    #pragma unroll
    for (int k=0;k<4;k++){ ax[k]=CA[2*k]; ay[k]=CA[2*k+1]; bx4[k]=CB[2*k]; by4[k]=CB[2*k+1]; }
    float d1x[4],d1y[4],d2x[4],d2y[4];
    #pragma unroll
    for (int k=0;k<4;k++){
        d1x[k]=ax[(k+1)&3]-ax[k];  d1y[k]=ay[(k+1)&3]-ay[k];
        d2x[k]=bx4[(k+1)&3]-bx4[k]; d2y[k]=by4[(k+1)&3]-by4[k];
    }

    float px[24], py[24]; bool ok[24];
    #pragma unroll
    for (int i=0;i<4;i++){
        #pragma unroll
        for (int j=0;j<4;j++){
            float den  = crs(d1x[i],d1y[i],d2x[j],d2y[j]);
            float dfx  = bx4[j]-ax[i], dfy = by4[j]-ay[i];
            float dens = (fabsf(den) < EPSF) ? 1.0f : den;
            float t = crs(dfx,dfy,d2x[j],d2y[j]) / dens;
            float u = crs(dfx,dfy,d1x[i],d1y[i]) / dens;
            bool o = (fabsf(den) >= EPSF) && (t>=0.0f) && (t<=1.0f) && (u>=0.0f) && (u<=1.0f);
            px[4*i+j] = ax[i] + t*d1x[i];
            py[4*i+j] = ay[i] + t*d1y[i];
            ok[4*i+j] = o;
        }
    }
    #pragma unroll
    for (int p=0;p<4;p++){
        bool allpos=true, allneg=true;
        #pragma unroll
        for (int e=0;e<4;e++){
            float cr = crs(d2x[e],d2y[e], ax[p]-bx4[e], ay[p]-by4[e]);
            allpos = allpos && (cr >= -1e-6f);
            allneg = allneg && (cr <=  1e-6f);
        }
        ok[16+p] = allpos || allneg;
        px[16+p] = ax[p]; py[16+p] = ay[p];
    }
    #pragma unroll
    for (int p=0;p<4;p++){
        bool allpos=true, allneg=true;
        #pragma unroll
        for (int e=0;e<4;e++){
            float cr = crs(d1x[e],d1y[e], bx4[p]-ax[e], by4[p]-ay[e]);
            allpos = allpos && (cr >= -1e-6f);
            allneg = allneg && (cr <=  1e-6f);
        }
        ok[20+p] = allpos || allneg;
        px[20+p] = bx4[p]; py[20+p] = by4[p];
    }

    int nv = 0; float cx = 0.0f, cy = 0.0f;
    #pragma unroll
    for (int i=0;i<24;i++) if (ok[i]){ nv++; cx += px[i]; cy += py[i]; }
    if (nv < 3) return 0.0f;
    cx /= (float)nv;  cy /= (float)nv;

    // valid points + ONE centroid vertex at angle +0.0 (all parked points
    // in the reference collapse to this single insertion: cross(c,c)=0)
    float sxp[25], syp[25], sap[25];
    int cnt = 0;
    #pragma unroll
    for (int i=0;i<24;i++) if (ok[i]){
        sxp[cnt]=px[i]; syp[cnt]=py[i];
        sap[cnt]=atan2f(py[i]-cy, px[i]-cx);
        cnt++;
    }
    sxp[cnt]=cx; syp[cnt]=cy; sap[cnt]=0.0f; cnt++;

    for (int k=1;k<cnt;k++){             // stable insertion sort by angle
        float a0=sap[k], x0=sxp[k], y0=syp[k];
        int mo=k-1;
        while (mo>=0 && sap[mo] > a0){
            sap[mo+1]=sap[mo]; sxp[mo+1]=sxp[mo]; syp[mo+1]=syp[mo]; mo--;
        }
        sap[mo+1]=a0; sxp[mo+1]=x0; syp[mo+1]=y0;
    }
    float s = 0.0f;
    for (int i=0;i<cnt;i++){
        int j = (i+1<cnt) ? i+1 : 0;
        s += sxp[i]*syp[j] - syp[i]*sxp[j];
    }
    return 0.5f*fabsf(s);
}

// ---------------- kernel 2: all valid pairs -> suppression bitmask ----------------
__global__ void __launch_bounds__(256) k_pairs()
{
    int g   = blockIdx.x / SUBB;
    int sub = blockIdx.x % SUBB;
    int v = g_vcnt[g];
    int P = v*(v-1)/2;
    int base = g*NB;
    for (int p = sub*blockDim.x + threadIdx.x; p < P; p += SUBB*256){
        int j = (int)((1.0f + sqrtf(1.0f + 8.0f*(float)p))*0.5f);
        while (j*(j-1)/2 > p) j--;
        while ((j+1)*j/2 <= p) j++;
        int i = p - j*(j-1)/2;

        float4 mi = g_pmeta[base+i];
        float4 mj = g_pmeta[base+j];
        float aA = mi.z, aB = mj.z;
        float mn = fminf(aA,aB), sm = aA + aB;
        if (3.0f*mn <= sm*(1.0f - 1e-4f)) continue;      // IoU<=0.5 certain
        float dx = mi.x-mj.x, dy = mi.y-mj.y;
        float rr = mi.w+mj.w;
        if (dx*dx + dy*dy >= rr*rr) continue;            // disjoint
        float4 ca0 = g_pcorn4[(base+i)*2+0], ca1 = g_pcorn4[(base+i)*2+1];
        float4 cb0 = g_pcorn4[(base+j)*2+0], cb1 = g_pcorn4[(base+j)*2+1];
        float CA[8] = {ca0.x,ca0.y,ca0.z,ca0.w,ca1.x,ca1.y,ca1.z,ca1.w};
        float CB[8] = {cb0.x,cb0.y,cb0.z,cb0.w,cb1.x,cb1.y,cb1.z,cb1.w};
        float inter = inter_area_dev(CA, CB);
        float iou = inter / (aA + aB - inter + EPSF);
        if (iou > NMS_TH)
            atomicOr(&g_mask[(base+i)*MASKW + (j>>5)], 1u << (j&31));
    }
}

// ---------------- kernel 3: greedy — block-wise register-serial chain ----------------
__global__ void __launch_bounds__(256) k_greedy()
{
    __shared__ unsigned sm[NB*MASKW];
    __shared__ unsigned sblk[MASKW];
    int g = blockIdx.x;
    int t = threadIdx.x;
    int v = g_vcnt[g];

    for (int w = t; w < v*MASKW; w += 256) sm[w] = g_mask[g*NB*MASKW + w];
    if (t < MASKW) sblk[t] = 0u;
    __syncthreads();

    int B = (v + 31) & ~31;
    for (int r0 = t; r0 < B; r0 += 256){
        bool any = false;
        if (r0 < v){
            unsigned o = 0u;
            #pragma unroll
            for (int w=0;w<MASKW;w++) o |= sm[r0*MASKW+w];
            any = (o != 0u);
        }
        unsigned bal = __ballot_sync(FULLM, any);
        if ((t & 31) == 0) sblk[r0 >> 5] = bal;
    }
    __syncthreads();

    if (t < 32){
        int lane = t;
        unsigned sup = 0u;                       // lane b owns sup word b
        int nblk = (v + 31) >> 5;
        for (int b=0; b<nblk; b++){
            unsigned sb = sblk[b];
            if (sb == 0u) continue;              // no suppressors in block
            unsigned s = __shfl_sync(FULLM, sup, b);
            if (lane == 0){
                unsigned it = sb;                // ascending row order
                while (it){
                    int l = __ffs(it) - 1; it &= it - 1u;
                    if (!((s >> l) & 1u)) s |= sm[(b*32+l)*MASKW + b];
                }
            }
            s = __shfl_sync(FULLM, s, 0);
            unsigned kept = (~s) & sb;           // kept suppressor rows
            if (lane < MASKW){
                unsigned acc = 0u, it = kept;
                while (it){
                    int l = __ffs(it) - 1; it &= it - 1u;
                    acc |= sm[(b*32+l)*MASKW + lane];
                }
                sup |= acc;
            }
        }
        for (int base=0; base<v; base+=32){
            int tp = base + lane;
            int src = (tp < v) ? (tp>>5) : 0;
            unsigned wv = __shfl_sync(FULLM, sup, src);
            if (tp < v && !((wv >> (tp&31)) & 1u)){
                int n = g_vlist[g*NB+tp];
                g_kept[g*NB+n] = g_psc[g*NB+tp];
            }
        }
    }
}

// ---------------- kernel 4: per-image top-100 via histogram rank-select ----------------
__global__ void __launch_bounds__(512) k_topk(float* __restrict__ out, int out_size)
{
    __shared__ int hist[2048];
    __shared__ unsigned long long cand[CANDC];
    __shared__ int ccnt;
    __shared__ int s_thresh;
    __shared__ int warpsum[16];

    int b = blockIdx.x;
    int t = threadIdx.x;
    int lane = t & 31, wid = t >> 5;

    for (int i=t;i<2048;i+=512) hist[i]=0;
    if (t==0){ ccnt=0; s_thresh=-1; }
    __syncthreads();

    // pass 1: histogram over top-11 bits of (~ub) key
    for (int f=t; f<NFG*NB; f+=512){
        float sc = g_kept[b*NFG*NB + f];
        if (sc > 0.0f){
            unsigned kh = ~(__float_as_uint(sc) | 0x80000000u);
            atomicAdd(&hist[kh>>21], 1);
        }
    }
    __syncthreads();

    // prefix scan over 2048 bins, 4 bins/thread
    int h0=hist[t*4], h1=hist[t*4+1], h2=hist[t*4+2], h3=hist[t*4+3];
    int local = h0+h1+h2+h3;
    int x = local;
    #pragma unroll
    for (int o=1;o<32;o<<=1){ int y=__shfl_up_sync(FULLM,x,o); if (lane>=o) x+=y; }
    if (lane==31) warpsum[wid]=x;
    __syncthreads();
    if (wid==0){
        int y = (lane<16)? warpsum[lane] : 0;
        #pragma unroll
        for (int o=1;o<16;o<<=1){ int z=__shfl_up_sync(FULLM,y,o); if (lane>=o) y+=z; }
        if (lane<16) warpsum[lane]=y;
    }
    __syncthreads();
    int totalK = warpsum[15];
    int need = totalK < DET ? totalK : DET;
    int incl = x + ((wid>0)? warpsum[wid-1] : 0);
    int excl = incl - local;
    if (need > 0){
        int c0=excl+h0, c1=c0+h1, c2=c1+h2, c3=c2+h3;
        int tb=-1;
        if (excl<need && c0>=need) tb=t*4;
        else if (c0<need && c1>=need) tb=t*4+1;
        else if (c1<need && c2>=need) tb=t*4+2;
        else if (c2<need && c3>=need) tb=t*4+3;
        if (tb>=0) s_thresh = tb;                 // exactly one writer
    }
    __syncthreads();
    int T = s_thresh;

    // pass 2: compact candidates (bins <= T); count <= 99 + |bin T|
    if (T >= 0){
        for (int f=t; f<NFG*NB; f+=512){
            float sc = g_kept[b*NFG*NB + f];
            if (sc > 0.0f){
                unsigned kh = ~(__float_as_uint(sc) | 0x80000000u);
                if ((int)(kh>>21) <= T){
                    int p = atomicAdd(&ccnt, 1);
                    if (p < CANDC)
                        cand[p] = (((unsigned long long)kh) << 32) | (unsigned)f;
                }
            }
        }
    }
    __syncthreads();
    int Kc = ccnt < CANDC ? ccnt : CANDC;
    int P = 128;
    while (P < Kc) P <<= 1;                        // P <= CANDC
    for (int f = Kc + t; f < P; f += 512) cand[f] = 0xFFFFFFFFFFFFFFFFull;
    __syncthreads();

    for (int k=2;k<=P;k<<=1)
        for (int j=k>>1;j>0;j>>=1){
            for (int p=t;p<P;p+=512){
                int ixj = p ^ j;
                if (ixj > p){
                    unsigned long long A = cand[p], Bv = cand[ixj];
                    if ((A > Bv) == ((p & k) == 0)){ cand[p] = Bv; cand[ixj] = A; }
                }
            }
            __syncthreads();
        }

    if (t < DET){
        unsigned long long key = (t < Kc) ? cand[t] : 0xFFFFFFFFFFFFFFFFull;
        unsigned f  = (unsigned)(key & 0xFFFFFFFFull);
        unsigned ub = ~((unsigned)(key >> 32));
        unsigned bits = (ub & 0x80000000u) ? (ub ^ 0x80000000u) : ~ub;
        float sc = __uint_as_float(bits);
        bool okd = (t < Kc) && (sc > 0.0f);

        float vals[6] = {0.f,0.f,0.f,0.f,0.f,0.f};
        float lab = 0.0f;
        if (okd){
            int bi = b*NFG*NB + (int)f;
            #pragma unroll
            for (int kk=0;kk<5;kk++) vals[kk] = g_boxes[bi*5+kk];
            vals[5] = sc;
            lab = (float)((int)f / NB + 1);
        }
        int base = b*DET*6 + t*6;
        #pragma unroll
        for (int kk=0;kk<6;kk++) if (base+kk < out_size) out[base+kk] = vals[kk];
        int li = NIMG*DET*6 + b*DET + t;
        if (li < out_size) out[li] = lab;
    }
}

// ---------------- launcher ----------------
extern "C" void kernel_launch(void* const* d_in, const int* in_sizes, int n_in,
                              void* d_out, int out_size)
{
    const float* logits = (const float*)d_in[0];   // (768, 11)
    const float* reg    = (const float*)d_in[1];   // (768, 55)
    const float* rr     = (const float*)d_in[2];   // (768, 5)

    k_decsort<<<NGRP, 512>>>(logits, reg, rr);
    k_pairs  <<<NGRP*SUBB, 256>>>();
    k_greedy <<<NGRP, 256>>>();
    k_topk   <<<NIMG, 512>>>((float*)d_out, out_size);
}